// round 1
// baseline (speedup 1.0000x reference)
#include <cuda_runtime.h>
#include <cstdint>

// Problem constants
#define BB 4
#define TT 4096
#define DD 2048
#define MM (BB*TT)   // 16384 rows

// ---------------- scratch (device globals; no allocation allowed) ----------
__device__ float g_kmix[(size_t)MM*DD];
__device__ float g_vmix[(size_t)MM*DD];
__device__ float g_rmix[(size_t)MM*DD];
__device__ float g_k   [(size_t)MM*DD];
__device__ float g_v   [(size_t)MM*DD];
__device__ float g_r   [(size_t)MM*DD];
__device__ float g_wkvr[(size_t)MM*DD];

// ---------------- mix kernel: time-shift + lerp + silu(r) ------------------
__global__ void mix_kernel(const float* __restrict__ x,
                           const float* __restrict__ tmk,
                           const float* __restrict__ tmv,
                           const float* __restrict__ tmr,
                           float* __restrict__ km,
                           float* __restrict__ vm,
                           float* __restrict__ rm) {
    int i4 = blockIdx.x * blockDim.x + threadIdx.x;
    if (i4 >= MM * DD / 4) return;
    size_t i = (size_t)i4 * 4;
    int m = (int)(i / DD);
    int d = (int)(i % DD);
    int t = m % TT;
    float4 xv = *(const float4*)(x + i);
    float4 xs = (t > 0) ? *(const float4*)(x + i - DD) : make_float4(0.f, 0.f, 0.f, 0.f);
    float4 mk = *(const float4*)(tmk + d);
    float4 mv = *(const float4*)(tmv + d);
    float4 mr = *(const float4*)(tmr + d);

    float4 o;
    o.x = xv.x * mk.x + xs.x * (1.f - mk.x);
    o.y = xv.y * mk.y + xs.y * (1.f - mk.y);
    o.z = xv.z * mk.z + xs.z * (1.f - mk.z);
    o.w = xv.w * mk.w + xs.w * (1.f - mk.w);
    *(float4*)(km + i) = o;

    o.x = xv.x * mv.x + xs.x * (1.f - mv.x);
    o.y = xv.y * mv.y + xs.y * (1.f - mv.y);
    o.z = xv.z * mv.z + xs.z * (1.f - mv.z);
    o.w = xv.w * mv.w + xs.w * (1.f - mv.w);
    *(float4*)(vm + i) = o;

    float s;
    s = xv.x * mr.x + xs.x * (1.f - mr.x); o.x = s / (1.f + __expf(-s));
    s = xv.y * mr.y + xs.y * (1.f - mr.y); o.y = s / (1.f + __expf(-s));
    s = xv.z * mr.z + xs.z * (1.f - mr.z); o.z = s / (1.f + __expf(-s));
    s = xv.w * mr.w + xs.w * (1.f - mr.w); o.w = s / (1.f + __expf(-s));
    *(float4*)(rm + i) = o;
}

// ---------------- TF32 GEMM: C[m,n] = sum_k A[m,k]*W[n,k] + bias[n] --------
// A: [MM, DD] row-major. W: [DD, DD] row-major (torch Linear weight: [out,in]).
constexpr int BM = 128, BN = 128, BK = 32;
constexpr int LDSM = 36;                 // padded row stride (floats)
constexpr int STAGE_F = BM * LDSM;       // floats per stage per matrix
constexpr int SMEM_BYTES = 4 * STAGE_F * 4;  // 2 stages * (A + B) * 4B = 73728

__device__ __forceinline__ uint32_t f2tf(float x) {
    uint32_t u;
    asm volatile("cvt.rna.tf32.f32 %0, %1;" : "=r"(u) : "f"(x));
    return u;
}

__device__ __forceinline__ void cp16(uint32_t dst, const void* src) {
    asm volatile("cp.async.cg.shared.global [%0], [%1], 16;" :: "r"(dst), "l"(src));
}

__global__ __launch_bounds__(256)
void gemm_tf32(const float* __restrict__ A, const float* __restrict__ W,
               const float* __restrict__ bias, float* __restrict__ C) {
    extern __shared__ float smem[];
    float* As = smem;                 // [2][BM][LDSM]
    float* Bs = smem + 2 * STAGE_F;   // [2][BN][LDSM]
    const int K = DD, N = DD;

    int tid  = threadIdx.x;
    int m0   = blockIdx.y * BM;
    int n0   = blockIdx.x * BN;
    int warp = tid >> 5, lane = tid & 31;
    int wm = warp >> 2, wn = warp & 3;      // 2 x 4 warp grid
    int g  = lane >> 2, tg = lane & 3;      // mma lane decomposition

    float acc[4][4][4];
#pragma unroll
    for (int a = 0; a < 4; a++)
#pragma unroll
        for (int b = 0; b < 4; b++)
#pragma unroll
            for (int c = 0; c < 4; c++) acc[a][b][c] = 0.f;

    uint32_t asBase = (uint32_t)__cvta_generic_to_shared(As);
    uint32_t bsBase = (uint32_t)__cvta_generic_to_shared(Bs);

    auto load_stage = [&](int s, int ko) {
#pragma unroll
        for (int i = 0; i < 4; i++) {
            int c  = tid + i * 256;        // 1024 16B-chunks per matrix
            int r  = c >> 3;
            int cf = (c & 7) * 4;
            cp16(asBase + (uint32_t)(s * STAGE_F + r * LDSM + cf) * 4,
                 A + (size_t)(m0 + r) * K + ko + cf);
            cp16(bsBase + (uint32_t)(s * STAGE_F + r * LDSM + cf) * 4,
                 W + (size_t)(n0 + r) * K + ko + cf);
        }
        asm volatile("cp.async.commit_group;");
    };

    load_stage(0, 0);
    const int KT = K / BK;   // 64
    for (int kt = 0; kt < KT; kt++) {
        if (kt + 1 < KT) {
            load_stage((kt + 1) & 1, (kt + 1) * BK);
            asm volatile("cp.async.wait_group 1;");
        } else {
            asm volatile("cp.async.wait_group 0;");
        }
        __syncthreads();
        const float* as = As + (kt & 1) * STAGE_F;
        const float* bs = Bs + (kt & 1) * STAGE_F;
#pragma unroll
        for (int ks = 0; ks < 4; ks++) {
            int kk = ks * 8;
            uint32_t af[4][4], bf[4][2];
#pragma unroll
            for (int mt = 0; mt < 4; mt++) {
                int mr = wm * 64 + mt * 16 + g;
                af[mt][0] = f2tf(as[(size_t)mr        * LDSM + kk + tg]);
                af[mt][1] = f2tf(as[(size_t)(mr + 8)  * LDSM + kk + tg]);
                af[mt][2] = f2tf(as[(size_t)mr        * LDSM + kk + tg + 4]);
                af[mt][3] = f2tf(as[(size_t)(mr + 8)  * LDSM + kk + tg + 4]);
            }
#pragma unroll
            for (int nt = 0; nt < 4; nt++) {
                int nr = wn * 32 + nt * 8 + g;
                bf[nt][0] = f2tf(bs[(size_t)nr * LDSM + kk + tg]);
                bf[nt][1] = f2tf(bs[(size_t)nr * LDSM + kk + tg + 4]);
            }
#pragma unroll
            for (int mt = 0; mt < 4; mt++)
#pragma unroll
                for (int nt = 0; nt < 4; nt++) {
                    asm volatile(
                        "mma.sync.aligned.m16n8k8.row.col.f32.tf32.tf32.f32 "
                        "{%0,%1,%2,%3}, {%4,%5,%6,%7}, {%8,%9}, {%0,%1,%2,%3};"
                        : "+f"(acc[mt][nt][0]), "+f"(acc[mt][nt][1]),
                          "+f"(acc[mt][nt][2]), "+f"(acc[mt][nt][3])
                        : "r"(af[mt][0]), "r"(af[mt][1]), "r"(af[mt][2]), "r"(af[mt][3]),
                          "r"(bf[nt][0]), "r"(bf[nt][1]));
                }
        }
        __syncthreads();
    }

    // epilogue: add bias, store float2 pairs
#pragma unroll
    for (int mt = 0; mt < 4; mt++) {
#pragma unroll
        for (int nt = 0; nt < 4; nt++) {
            int m = m0 + wm * 64 + mt * 16 + g;
            int n = n0 + wn * 32 + nt * 8 + tg * 2;
            float b0 = bias[n], b1 = bias[n + 1];
            float2 v0 = make_float2(acc[mt][nt][0] + b0, acc[mt][nt][1] + b1);
            float2 v1 = make_float2(acc[mt][nt][2] + b0, acc[mt][nt][3] + b1);
            *(float2*)(C + (size_t)m * N + n)       = v0;
            *(float2*)(C + (size_t)(m + 8) * N + n) = v1;
        }
    }
}

// ---------------- WKV scan (fused * r) -------------------------------------
__global__ void wkv_kernel(const float* __restrict__ k, const float* __restrict__ v,
                           const float* __restrict__ r, const float* __restrict__ u,
                           const float* __restrict__ w, float* __restrict__ out) {
    int idx = blockIdx.x * blockDim.x + threadIdx.x;
    if (idx >= BB * DD) return;
    int b = idx / DD, d = idx % DD;
    float uu = u[d], ww = w[d];
    size_t base = (size_t)b * TT * DD + d;
    float a = 0.f, bden = 0.f;
    for (int t = 0; t < TT; t++) {
        size_t off = base + (size_t)t * DD;
        float kt = k[off], vt = v[off];
        float mx = fmaxf(uu + kt, ww);
        float e1 = __expf(-ww - mx);
        float e2 = __expf(uu + kt - mx);
        a    = fmaf(e1, a,    e2 * vt);
        bden = fmaf(e1, bden, e2);
        out[off] = (a / bden) * r[off];
    }
}

// ---------------- launch ----------------------------------------------------
extern "C" void kernel_launch(void* const* d_in, const int* in_sizes, int n_in,
                              void* d_out, int out_size) {
    (void)in_sizes; (void)n_in; (void)out_size;
    const float* x   = (const float*)d_in[0];
    const float* Wk  = (const float*)d_in[1];
    const float* bk  = (const float*)d_in[2];
    const float* Wv  = (const float*)d_in[3];
    const float* bv  = (const float*)d_in[4];
    const float* Wr  = (const float*)d_in[5];
    const float* br  = (const float*)d_in[6];
    const float* Wo  = (const float*)d_in[7];
    const float* bo  = (const float*)d_in[8];
    const float* tmk = (const float*)d_in[9];
    const float* tmv = (const float*)d_in[10];
    const float* tmr = (const float*)d_in[11];
    const float* u   = (const float*)d_in[12];
    const float* w   = (const float*)d_in[13];
    float* out = (float*)d_out;

    float *kmix, *vmix, *rmix, *kb, *vb, *rb, *wkvr;
    cudaGetSymbolAddress((void**)&kmix, g_kmix);
    cudaGetSymbolAddress((void**)&vmix, g_vmix);
    cudaGetSymbolAddress((void**)&rmix, g_rmix);
    cudaGetSymbolAddress((void**)&kb,   g_k);
    cudaGetSymbolAddress((void**)&vb,   g_v);
    cudaGetSymbolAddress((void**)&rb,   g_r);
    cudaGetSymbolAddress((void**)&wkvr, g_wkvr);

    cudaFuncSetAttribute(gemm_tf32, cudaFuncAttributeMaxDynamicSharedMemorySize, SMEM_BYTES);

    int mixBlocks = (MM * DD / 4 + 255) / 256;
    mix_kernel<<<mixBlocks, 256>>>(x, tmk, tmv, tmr, kmix, vmix, rmix);

    dim3 ggrid(DD / BN, MM / BM);   // (16, 128)
    gemm_tf32<<<ggrid, 256, SMEM_BYTES>>>(kmix, Wk, bk, kb);
    gemm_tf32<<<ggrid, 256, SMEM_BYTES>>>(vmix, Wv, bv, vb);
    gemm_tf32<<<ggrid, 256, SMEM_BYTES>>>(rmix, Wr, br, rb);

    wkv_kernel<<<(BB * DD + 255) / 256, 256>>>(kb, vb, rb, u, w, wkvr);

    gemm_tf32<<<ggrid, 256, SMEM_BYTES>>>(wkvr, Wo, bo, out);
}

// round 2
// speedup vs baseline: 2.0813x; 2.0813x over previous
#include <cuda_runtime.h>
#include <cstdint>

#define BB 4
#define TT 4096
#define DD 2048
#define MM (BB*TT)   // 16384
#define NC 64        // scan chunks
#define LC (TT/NC)   // 64 steps per chunk

// ---------------- scratch (device globals) ----------------------------------
__device__ float g_kmix[(size_t)MM*DD];
__device__ float g_vmix[(size_t)MM*DD];
__device__ float g_rmix[(size_t)MM*DD];
__device__ float g_k   [(size_t)MM*DD];
__device__ float g_v   [(size_t)MM*DD];
__device__ float g_r   [(size_t)MM*DD];
__device__ float g_wkvr[(size_t)MM*DD];
__device__ float g_W   [4][(size_t)DD*DD];     // tf32-converted weights
__device__ float g_P [(size_t)BB*NC*DD];
__device__ float g_A [(size_t)BB*NC*DD];
__device__ float g_Bc[(size_t)BB*NC*DD];
__device__ float g_iA[(size_t)BB*NC*DD];
__device__ float g_iB[(size_t)BB*NC*DD];

__device__ __forceinline__ uint32_t f2tf(float x) {
    uint32_t u;
    asm volatile("cvt.rna.tf32.f32 %0, %1;" : "=r"(u) : "f"(x));
    return u;
}
__device__ __forceinline__ float f2tf_f(float x) { return __uint_as_float(f2tf(x)); }

// ---------------- weight convert (fp32 -> tf32 bits) ------------------------
__global__ void wconv_kernel(const float* __restrict__ in, float* __restrict__ out) {
    int i = blockIdx.x * blockDim.x + threadIdx.x;   // over DD*DD/4
    if (i >= DD * DD / 4) return;
    float4 v = ((const float4*)in)[i];
    v.x = f2tf_f(v.x); v.y = f2tf_f(v.y); v.z = f2tf_f(v.z); v.w = f2tf_f(v.w);
    ((float4*)out)[i] = v;
}

// ---------------- mix: time-shift + lerp (+silu for r), emit tf32 bits ------
__global__ void mix_kernel(const float* __restrict__ x,
                           const float* __restrict__ tmk,
                           const float* __restrict__ tmv,
                           const float* __restrict__ tmr,
                           float* __restrict__ km,
                           float* __restrict__ vm,
                           float* __restrict__ rm) {
    int i4 = blockIdx.x * blockDim.x + threadIdx.x;
    if (i4 >= MM * DD / 4) return;
    size_t i = (size_t)i4 * 4;
    int m = (int)(i / DD);
    int d = (int)(i % DD);
    int t = m % TT;
    float4 xv = *(const float4*)(x + i);
    float4 xs = (t > 0) ? *(const float4*)(x + i - DD) : make_float4(0.f, 0.f, 0.f, 0.f);
    float4 mk = *(const float4*)(tmk + d);
    float4 mv = *(const float4*)(tmv + d);
    float4 mr = *(const float4*)(tmr + d);

    float4 o;
    o.x = f2tf_f(xv.x * mk.x + xs.x * (1.f - mk.x));
    o.y = f2tf_f(xv.y * mk.y + xs.y * (1.f - mk.y));
    o.z = f2tf_f(xv.z * mk.z + xs.z * (1.f - mk.z));
    o.w = f2tf_f(xv.w * mk.w + xs.w * (1.f - mk.w));
    *(float4*)(km + i) = o;

    o.x = f2tf_f(xv.x * mv.x + xs.x * (1.f - mv.x));
    o.y = f2tf_f(xv.y * mv.y + xs.y * (1.f - mv.y));
    o.z = f2tf_f(xv.z * mv.z + xs.z * (1.f - mv.z));
    o.w = f2tf_f(xv.w * mv.w + xs.w * (1.f - mv.w));
    *(float4*)(vm + i) = o;

    float s;
    s = xv.x * mr.x + xs.x * (1.f - mr.x); o.x = f2tf_f(s / (1.f + __expf(-s)));
    s = xv.y * mr.y + xs.y * (1.f - mr.y); o.y = f2tf_f(s / (1.f + __expf(-s)));
    s = xv.z * mr.z + xs.z * (1.f - mr.z); o.z = f2tf_f(s / (1.f + __expf(-s)));
    s = xv.w * mr.w + xs.w * (1.f - mr.w); o.w = f2tf_f(s / (1.f + __expf(-s)));
    *(float4*)(rm + i) = o;
}

// ---------------- TF32 GEMM (inputs pre-converted to tf32 bits) -------------
// C[m,n] = sum_k A[m,k]*W[n,k] + bias[n];  A:[MM,DD], W:[DD,DD] row-major
constexpr int BM = 128, BN = 128, BK = 32, STAGES = 3;
constexpr int STAGE_F = BM * BK;                         // 4096 floats
constexpr int SMEM_BYTES = STAGES * 2 * STAGE_F * 4;     // 98304 B

__device__ __forceinline__ void cp16(uint32_t dst, const void* src) {
    asm volatile("cp.async.cg.shared.global [%0], [%1], 16;" :: "r"(dst), "l"(src));
}

__global__ __launch_bounds__(256, 2)
void gemm_tf32(const float* __restrict__ A, const float* __restrict__ W,
               const float* __restrict__ bias, float* __restrict__ C) {
    extern __shared__ float smem[];
    float* As = smem;                       // [STAGES][BM][BK], xor-swizzled
    float* Bs = smem + STAGES * STAGE_F;    // [STAGES][BN][BK]
    const int K = DD, N = DD;

    int tid  = threadIdx.x;
    int m0   = blockIdx.y * BM;
    int n0   = blockIdx.x * BN;
    int warp = tid >> 5, lane = tid & 31;
    int wm = warp >> 2, wn = warp & 3;
    int g  = lane >> 2, tg = lane & 3;
    int key = g * 4;                        // xor swizzle key (rows: low3 bits == g)

    float acc[4][4][4];
#pragma unroll
    for (int a = 0; a < 4; a++)
#pragma unroll
        for (int b = 0; b < 4; b++)
#pragma unroll
            for (int c = 0; c < 4; c++) acc[a][b][c] = 0.f;

    uint32_t asB = (uint32_t)__cvta_generic_to_shared(As);
    uint32_t bsB = (uint32_t)__cvta_generic_to_shared(Bs);

    auto load_stage = [&](int s, int ko) {
#pragma unroll
        for (int i = 0; i < 4; i++) {
            int c  = tid + i * 256;          // 1024 16B chunks per matrix
            int r  = c >> 3;
            int cf = (c & 7) * 4;
            int pc = cf ^ ((r & 7) * 4);     // swizzled column
            cp16(asB + (uint32_t)(s * STAGE_F + r * BK + pc) * 4,
                 A + (size_t)(m0 + r) * K + ko + cf);
            cp16(bsB + (uint32_t)(s * STAGE_F + r * BK + pc) * 4,
                 W + (size_t)(n0 + r) * K + ko + cf);
        }
        asm volatile("cp.async.commit_group;");
    };

    load_stage(0, 0);
    load_stage(1, BK);
    const int KT = K / BK;   // 64
    for (int kt = 0; kt < KT; kt++) {
        if (kt < KT - 1) asm volatile("cp.async.wait_group 1;");
        else             asm volatile("cp.async.wait_group 0;");
        __syncthreads();
        if (kt + 2 < KT) load_stage((kt + 2) % 3, (kt + 2) * BK);

        const float* as = As + (kt % 3) * STAGE_F;
        const float* bs = Bs + (kt % 3) * STAGE_F;
#pragma unroll
        for (int ks = 0; ks < 4; ks++) {
            int kk = ks * 8;
            int c0 = (kk + tg) ^ key;
            int c1 = (kk + tg + 4) ^ key;
            uint32_t af[4][4], bf[4][2];
#pragma unroll
            for (int mt = 0; mt < 4; mt++) {
                int mr = wm * 64 + mt * 16 + g;
                af[mt][0] = __float_as_uint(as[(mr)     * BK + c0]);
                af[mt][1] = __float_as_uint(as[(mr + 8) * BK + c0]);
                af[mt][2] = __float_as_uint(as[(mr)     * BK + c1]);
                af[mt][3] = __float_as_uint(as[(mr + 8) * BK + c1]);
            }
#pragma unroll
            for (int nt = 0; nt < 4; nt++) {
                int nr = wn * 32 + nt * 8 + g;
                bf[nt][0] = __float_as_uint(bs[nr * BK + c0]);
                bf[nt][1] = __float_as_uint(bs[nr * BK + c1]);
            }
#pragma unroll
            for (int mt = 0; mt < 4; mt++)
#pragma unroll
                for (int nt = 0; nt < 4; nt++) {
                    asm volatile(
                        "mma.sync.aligned.m16n8k8.row.col.f32.tf32.tf32.f32 "
                        "{%0,%1,%2,%3}, {%4,%5,%6,%7}, {%8,%9}, {%0,%1,%2,%3};"
                        : "+f"(acc[mt][nt][0]), "+f"(acc[mt][nt][1]),
                          "+f"(acc[mt][nt][2]), "+f"(acc[mt][nt][3])
                        : "r"(af[mt][0]), "r"(af[mt][1]), "r"(af[mt][2]), "r"(af[mt][3]),
                          "r"(bf[nt][0]), "r"(bf[nt][1]));
                }
        }
    }

#pragma unroll
    for (int mt = 0; mt < 4; mt++) {
#pragma unroll
        for (int nt = 0; nt < 4; nt++) {
            int m = m0 + wm * 64 + mt * 16 + g;
            int n = n0 + wn * 32 + nt * 8 + tg * 2;
            float b0 = bias[n], b1 = bias[n + 1];
            float2 v0 = make_float2(acc[mt][nt][0] + b0, acc[mt][nt][1] + b1);
            float2 v1 = make_float2(acc[mt][nt][2] + b0, acc[mt][nt][3] + b1);
            *(float2*)(C + (size_t)m * N + n)       = v0;
            *(float2*)(C + (size_t)(m + 8) * N + n) = v1;
        }
    }
}

// ---------------- chunked WKV scan ------------------------------------------
// pass1: per-chunk summaries (P = prod e1, local A, local B) from zero state
__global__ void wkv_pass1(const float* __restrict__ k, const float* __restrict__ v,
                          const float* __restrict__ u, const float* __restrict__ w,
                          float* __restrict__ P, float* __restrict__ A,
                          float* __restrict__ Bc) {
    int idx = blockIdx.x * blockDim.x + threadIdx.x;
    if (idx >= BB * NC * DD) return;
    int d = idx % DD;
    int rest = idx / DD;
    int c = rest % NC;
    int b = rest / NC;
    float uu = u[d], ww = w[d];
    size_t base = ((size_t)b * TT + (size_t)c * LC) * DD + d;
    float Pp = 1.f, Aa = 0.f, Bb = 0.f;
#pragma unroll 4
    for (int t = 0; t < LC; t++) {
        size_t off = base + (size_t)t * DD;
        float kt = k[off], vt = v[off];
        float mx = fmaxf(uu + kt, ww);
        float e1 = __expf(-ww - mx);
        float e2 = __expf(uu + kt - mx);
        Aa = fmaf(e1, Aa, e2 * vt);
        Bb = fmaf(e1, Bb, e2);
        Pp *= e1;
    }
    size_t o = ((size_t)b * NC + c) * DD + d;
    P[o] = Pp; A[o] = Aa; Bc[o] = Bb;
}

// combine: sequential prefix over the NC chunk summaries -> init states
__global__ void wkv_combine(const float* __restrict__ P, const float* __restrict__ A,
                            const float* __restrict__ Bc,
                            float* __restrict__ iA, float* __restrict__ iB) {
    int idx = blockIdx.x * blockDim.x + threadIdx.x;
    if (idx >= BB * DD) return;
    int d = idx % DD, b = idx / DD;
    float a = 0.f, bd = 0.f;
    for (int c = 0; c < NC; c++) {
        size_t o = ((size_t)b * NC + c) * DD + d;
        iA[o] = a; iB[o] = bd;
        a  = fmaf(P[o], a,  A[o]);
        bd = fmaf(P[o], bd, Bc[o]);
    }
}

// pass3: replay each chunk from true init state; emit (a/b)*r as tf32 bits
__global__ void wkv_pass3(const float* __restrict__ k, const float* __restrict__ v,
                          const float* __restrict__ r,
                          const float* __restrict__ u, const float* __restrict__ w,
                          const float* __restrict__ iA, const float* __restrict__ iB,
                          float* __restrict__ out) {
    int idx = blockIdx.x * blockDim.x + threadIdx.x;
    if (idx >= BB * NC * DD) return;
    int d = idx % DD;
    int rest = idx / DD;
    int c = rest % NC;
    int b = rest / NC;
    float uu = u[d], ww = w[d];
    size_t base = ((size_t)b * TT + (size_t)c * LC) * DD + d;
    size_t o = ((size_t)b * NC + c) * DD + d;
    float a = iA[o], bd = iB[o];
#pragma unroll 4
    for (int t = 0; t < LC; t++) {
        size_t off = base + (size_t)t * DD;
        float kt = k[off], vt = v[off];
        float mx = fmaxf(uu + kt, ww);
        float e1 = __expf(-ww - mx);
        float e2 = __expf(uu + kt - mx);
        a  = fmaf(e1, a,  e2 * vt);
        bd = fmaf(e1, bd, e2);
        out[off] = f2tf_f((a / bd) * r[off]);
    }
}

// ---------------- launch ----------------------------------------------------
extern "C" void kernel_launch(void* const* d_in, const int* in_sizes, int n_in,
                              void* d_out, int out_size) {
    (void)in_sizes; (void)n_in; (void)out_size;
    const float* x   = (const float*)d_in[0];
    const float* Wk  = (const float*)d_in[1];
    const float* bk  = (const float*)d_in[2];
    const float* Wv  = (const float*)d_in[3];
    const float* bv  = (const float*)d_in[4];
    const float* Wr  = (const float*)d_in[5];
    const float* br  = (const float*)d_in[6];
    const float* Wo  = (const float*)d_in[7];
    const float* bo  = (const float*)d_in[8];
    const float* tmk = (const float*)d_in[9];
    const float* tmv = (const float*)d_in[10];
    const float* tmr = (const float*)d_in[11];
    const float* u   = (const float*)d_in[12];
    const float* w   = (const float*)d_in[13];
    float* out = (float*)d_out;

    float *kmix, *vmix, *rmix, *kb, *vb, *rb, *wkvr, *Wc, *P, *A, *Bc, *iA, *iB;
    cudaGetSymbolAddress((void**)&kmix, g_kmix);
    cudaGetSymbolAddress((void**)&vmix, g_vmix);
    cudaGetSymbolAddress((void**)&rmix, g_rmix);
    cudaGetSymbolAddress((void**)&kb,   g_k);
    cudaGetSymbolAddress((void**)&vb,   g_v);
    cudaGetSymbolAddress((void**)&rb,   g_r);
    cudaGetSymbolAddress((void**)&wkvr, g_wkvr);
    cudaGetSymbolAddress((void**)&Wc,   g_W);
    cudaGetSymbolAddress((void**)&P,    g_P);
    cudaGetSymbolAddress((void**)&A,    g_A);
    cudaGetSymbolAddress((void**)&Bc,   g_Bc);
    cudaGetSymbolAddress((void**)&iA,   g_iA);
    cudaGetSymbolAddress((void**)&iB,   g_iB);
    float* Wkc = Wc + 0 * (size_t)DD * DD;
    float* Wvc = Wc + 1 * (size_t)DD * DD;
    float* Wrc = Wc + 2 * (size_t)DD * DD;
    float* Woc = Wc + 3 * (size_t)DD * DD;

    cudaFuncSetAttribute(gemm_tf32, cudaFuncAttributeMaxDynamicSharedMemorySize, SMEM_BYTES);

    int wcBlocks = (DD * DD / 4 + 255) / 256;
    wconv_kernel<<<wcBlocks, 256>>>(Wk, Wkc);
    wconv_kernel<<<wcBlocks, 256>>>(Wv, Wvc);
    wconv_kernel<<<wcBlocks, 256>>>(Wr, Wrc);
    wconv_kernel<<<wcBlocks, 256>>>(Wo, Woc);

    int mixBlocks = (MM * DD / 4 + 255) / 256;
    mix_kernel<<<mixBlocks, 256>>>(x, tmk, tmv, tmr, kmix, vmix, rmix);

    dim3 ggrid(DD / BN, MM / BM);   // (16, 128)
    gemm_tf32<<<ggrid, 256, SMEM_BYTES>>>(kmix, Wkc, bk, kb);
    gemm_tf32<<<ggrid, 256, SMEM_BYTES>>>(vmix, Wvc, bv, vb);
    gemm_tf32<<<ggrid, 256, SMEM_BYTES>>>(rmix, Wrc, br, rb);

    int scanThreads = BB * NC * DD;   // 524288
    wkv_pass1<<<scanThreads / 256, 256>>>(kb, vb, u, w, P, A, Bc);
    wkv_combine<<<(BB * DD + 255) / 256, 256>>>(P, A, Bc, iA, iB);
    wkv_pass3<<<scanThreads / 256, 256>>>(kb, vb, rb, u, w, iA, iB, wkvr);

    gemm_tf32<<<ggrid, 256, SMEM_BYTES>>>(wkvr, Woc, bo, out);
}

// round 3
// speedup vs baseline: 2.2193x; 1.0663x over previous
#include <cuda_runtime.h>
#include <cstdint>

#define BB 4
#define TT 4096
#define DD 2048
#define MM (BB*TT)   // 16384
#define NC 64        // scan chunks
#define LC (TT/NC)   // 64 steps per chunk

// ---------------- scratch (device globals) ----------------------------------
__device__ float g_kmix[(size_t)MM*DD];
__device__ float g_vmix[(size_t)MM*DD];
__device__ float g_rmix[(size_t)MM*DD];
__device__ float g_k   [(size_t)MM*DD];
__device__ float g_v   [(size_t)MM*DD];
__device__ float g_r   [(size_t)MM*DD];
__device__ float g_wkvr[(size_t)MM*DD];
__device__ float g_W   [4][(size_t)DD*DD];     // tf32-converted weights
__device__ float g_P [(size_t)BB*NC*DD];
__device__ float g_A [(size_t)BB*NC*DD];
__device__ float g_Bc[(size_t)BB*NC*DD];
__device__ float g_iA[(size_t)BB*NC*DD];
__device__ float g_iB[(size_t)BB*NC*DD];

__device__ __forceinline__ uint32_t f2tf(float x) {
    uint32_t u;
    asm volatile("cvt.rna.tf32.f32 %0, %1;" : "=r"(u) : "f"(x));
    return u;
}
__device__ __forceinline__ float f2tf_f(float x) { return __uint_as_float(f2tf(x)); }

// ---------------- weight convert (fp32 -> tf32 bits), all 4 in one launch ---
__global__ void wconv_kernel(const float* __restrict__ w0, const float* __restrict__ w1,
                             const float* __restrict__ w2, const float* __restrict__ w3,
                             float* __restrict__ out) {
    int i = blockIdx.x * blockDim.x + threadIdx.x;   // over DD*DD/4
    if (i >= DD * DD / 4) return;
    const float* src = (blockIdx.y == 0) ? w0 : (blockIdx.y == 1) ? w1 :
                       (blockIdx.y == 2) ? w2 : w3;
    float4 v = ((const float4*)src)[i];
    v.x = f2tf_f(v.x); v.y = f2tf_f(v.y); v.z = f2tf_f(v.z); v.w = f2tf_f(v.w);
    ((float4*)(out + (size_t)blockIdx.y * DD * DD))[i] = v;
}

// ---------------- mix: time-shift + lerp (+silu for r), emit tf32 bits ------
__global__ void mix_kernel(const float* __restrict__ x,
                           const float* __restrict__ tmk,
                           const float* __restrict__ tmv,
                           const float* __restrict__ tmr,
                           float* __restrict__ km,
                           float* __restrict__ vm,
                           float* __restrict__ rm) {
    int i4 = blockIdx.x * blockDim.x + threadIdx.x;
    if (i4 >= MM * DD / 4) return;
    size_t i = (size_t)i4 * 4;
    int m = (int)(i / DD);
    int d = (int)(i % DD);
    int t = m % TT;
    float4 xv = *(const float4*)(x + i);
    float4 xs = (t > 0) ? *(const float4*)(x + i - DD) : make_float4(0.f, 0.f, 0.f, 0.f);
    float4 mk = *(const float4*)(tmk + d);
    float4 mv = *(const float4*)(tmv + d);
    float4 mr = *(const float4*)(tmr + d);

    float4 o;
    o.x = f2tf_f(xv.x * mk.x + xs.x * (1.f - mk.x));
    o.y = f2tf_f(xv.y * mk.y + xs.y * (1.f - mk.y));
    o.z = f2tf_f(xv.z * mk.z + xs.z * (1.f - mk.z));
    o.w = f2tf_f(xv.w * mk.w + xs.w * (1.f - mk.w));
    *(float4*)(km + i) = o;

    o.x = f2tf_f(xv.x * mv.x + xs.x * (1.f - mv.x));
    o.y = f2tf_f(xv.y * mv.y + xs.y * (1.f - mv.y));
    o.z = f2tf_f(xv.z * mv.z + xs.z * (1.f - mv.z));
    o.w = f2tf_f(xv.w * mv.w + xs.w * (1.f - mv.w));
    *(float4*)(vm + i) = o;

    float s;
    s = xv.x * mr.x + xs.x * (1.f - mr.x); o.x = f2tf_f(s / (1.f + __expf(-s)));
    s = xv.y * mr.y + xs.y * (1.f - mr.y); o.y = f2tf_f(s / (1.f + __expf(-s)));
    s = xv.z * mr.z + xs.z * (1.f - mr.z); o.z = f2tf_f(s / (1.f + __expf(-s)));
    s = xv.w * mr.w + xs.w * (1.f - mr.w); o.w = f2tf_f(s / (1.f + __expf(-s)));
    *(float4*)(rm + i) = o;
}

// ---------------- TF32 GEMM (inputs pre-converted to tf32 bits) -------------
// C[m,n] = sum_k A[m,k]*W[n,k] + bias[n];  A:[MM,DD], W:[DD,DD] row-major
// BM=256, BN=128: 256 threads, 4x2 warp grid, 64x64 per warp.
constexpr int BM = 256, BN = 128, BK = 32, STAGES = 3;
constexpr int ASTAGE_F = BM * BK;   // 8192 floats
constexpr int BSTAGE_F = BN * BK;   // 4096 floats
constexpr int SMEM_BYTES = STAGES * (ASTAGE_F + BSTAGE_F) * 4;   // 147456 B

__device__ __forceinline__ void cp16(uint32_t dst, const void* src) {
    asm volatile("cp.async.cg.shared.global [%0], [%1], 16;" :: "r"(dst), "l"(src));
}

__global__ __launch_bounds__(256, 1)
void gemm_tf32(const float* __restrict__ A, const float* __restrict__ W,
               const float* __restrict__ bias, float* __restrict__ C) {
    extern __shared__ float smem[];
    float* As = smem;                          // [STAGES][BM][BK] xor-swizzled
    float* Bs = smem + STAGES * ASTAGE_F;      // [STAGES][BN][BK]
    const int K = DD, N = DD;

    int tid  = threadIdx.x;
    int m0   = blockIdx.y * BM;
    int n0   = blockIdx.x * BN;
    int warp = tid >> 5, lane = tid & 31;
    int wm = warp >> 1, wn = warp & 1;          // 4 x 2 warp grid, 64x64 tiles
    int g  = lane >> 2, tg = lane & 3;
    int key = g * 4;                            // rows used by this thread ≡ g (mod 8)

    float acc[4][8][4];
#pragma unroll
    for (int a = 0; a < 4; a++)
#pragma unroll
        for (int b = 0; b < 8; b++)
#pragma unroll
            for (int c = 0; c < 4; c++) acc[a][b][c] = 0.f;

    uint32_t asB = (uint32_t)__cvta_generic_to_shared(As);
    uint32_t bsB = (uint32_t)__cvta_generic_to_shared(Bs);

    auto load_stage = [&](int s, int ko) {
#pragma unroll
        for (int i = 0; i < 8; i++) {           // A: 2048 16B chunks
            int c  = tid + i * 256;
            int r  = c >> 3;
            int cf = (c & 7) * 4;
            int pc = cf ^ ((r & 7) * 4);
            cp16(asB + (uint32_t)(s * ASTAGE_F + r * BK + pc) * 4,
                 A + (size_t)(m0 + r) * K + ko + cf);
        }
#pragma unroll
        for (int i = 0; i < 4; i++) {           // B: 1024 16B chunks
            int c  = tid + i * 256;
            int r  = c >> 3;
            int cf = (c & 7) * 4;
            int pc = cf ^ ((r & 7) * 4);
            cp16(bsB + (uint32_t)(s * BSTAGE_F + r * BK + pc) * 4,
                 W + (size_t)(n0 + r) * K + ko + cf);
        }
        asm volatile("cp.async.commit_group;");
    };

    load_stage(0, 0);
    load_stage(1, BK);
    const int KT = K / BK;   // 64
    for (int kt = 0; kt < KT; kt++) {
        if (kt < KT - 1) asm volatile("cp.async.wait_group 1;");
        else             asm volatile("cp.async.wait_group 0;");
        __syncthreads();
        if (kt + 2 < KT) load_stage((kt + 2) % 3, (kt + 2) * BK);

        const float* as = As + (kt % 3) * ASTAGE_F;
        const float* bs = Bs + (kt % 3) * BSTAGE_F;
#pragma unroll
        for (int ks = 0; ks < 4; ks++) {
            int kk = ks * 8;
            int c0 = (kk + tg) ^ key;
            int c1 = (kk + tg + 4) ^ key;
            uint32_t af[4][4], bf[8][2];
#pragma unroll
            for (int mt = 0; mt < 4; mt++) {
                int mr = wm * 64 + mt * 16 + g;
                af[mt][0] = __float_as_uint(as[(mr)     * BK + c0]);
                af[mt][1] = __float_as_uint(as[(mr + 8) * BK + c0]);
                af[mt][2] = __float_as_uint(as[(mr)     * BK + c1]);
                af[mt][3] = __float_as_uint(as[(mr + 8) * BK + c1]);
            }
#pragma unroll
            for (int nt = 0; nt < 8; nt++) {
                int nr = wn * 64 + nt * 8 + g;
                bf[nt][0] = __float_as_uint(bs[nr * BK + c0]);
                bf[nt][1] = __float_as_uint(bs[nr * BK + c1]);
            }
#pragma unroll
            for (int mt = 0; mt < 4; mt++)
#pragma unroll
                for (int nt = 0; nt < 8; nt++) {
                    asm volatile(
                        "mma.sync.aligned.m16n8k8.row.col.f32.tf32.tf32.f32 "
                        "{%0,%1,%2,%3}, {%4,%5,%6,%7}, {%8,%9}, {%0,%1,%2,%3};"
                        : "+f"(acc[mt][nt][0]), "+f"(acc[mt][nt][1]),
                          "+f"(acc[mt][nt][2]), "+f"(acc[mt][nt][3])
                        : "r"(af[mt][0]), "r"(af[mt][1]), "r"(af[mt][2]), "r"(af[mt][3]),
                          "r"(bf[nt][0]), "r"(bf[nt][1]));
                }
        }
    }

#pragma unroll
    for (int mt = 0; mt < 4; mt++) {
#pragma unroll
        for (int nt = 0; nt < 8; nt++) {
            int m = m0 + wm * 64 + mt * 16 + g;
            int n = n0 + wn * 64 + nt * 8 + tg * 2;
            float b0 = bias[n], b1 = bias[n + 1];
            float2 v0 = make_float2(acc[mt][nt][0] + b0, acc[mt][nt][1] + b1);
            float2 v1 = make_float2(acc[mt][nt][2] + b0, acc[mt][nt][3] + b1);
            *(float2*)(C + (size_t)m * N + n)       = v0;
            *(float2*)(C + (size_t)(m + 8) * N + n) = v1;
        }
    }
}

// ---------------- chunked WKV scan ------------------------------------------
__global__ void wkv_pass1(const float* __restrict__ k, const float* __restrict__ v,
                          const float* __restrict__ u, const float* __restrict__ w,
                          float* __restrict__ P, float* __restrict__ A,
                          float* __restrict__ Bc) {
    int idx = blockIdx.x * blockDim.x + threadIdx.x;
    if (idx >= BB * NC * DD) return;
    int d = idx % DD;
    int rest = idx / DD;
    int c = rest % NC;
    int b = rest / NC;
    float uu = u[d], ww = w[d];
    size_t base = ((size_t)b * TT + (size_t)c * LC) * DD + d;
    float Pp = 1.f, Aa = 0.f, Bb = 0.f;
#pragma unroll 4
    for (int t = 0; t < LC; t++) {
        size_t off = base + (size_t)t * DD;
        float kt = k[off], vt = v[off];
        float mx = fmaxf(uu + kt, ww);
        float e1 = __expf(-ww - mx);
        float e2 = __expf(uu + kt - mx);
        Aa = fmaf(e1, Aa, e2 * vt);
        Bb = fmaf(e1, Bb, e2);
        Pp *= e1;
    }
    size_t o = ((size_t)b * NC + c) * DD + d;
    P[o] = Pp; A[o] = Aa; Bc[o] = Bb;
}

__global__ void wkv_combine(const float* __restrict__ P, const float* __restrict__ A,
                            const float* __restrict__ Bc,
                            float* __restrict__ iA, float* __restrict__ iB) {
    int idx = blockIdx.x * blockDim.x + threadIdx.x;
    if (idx >= BB * DD) return;
    int d = idx % DD, b = idx / DD;
    float a = 0.f, bd = 0.f;
    for (int c = 0; c < NC; c++) {
        size_t o = ((size_t)b * NC + c) * DD + d;
        iA[o] = a; iB[o] = bd;
        a  = fmaf(P[o], a,  A[o]);
        bd = fmaf(P[o], bd, Bc[o]);
    }
}

__global__ void wkv_pass3(const float* __restrict__ k, const float* __restrict__ v,
                          const float* __restrict__ r,
                          const float* __restrict__ u, const float* __restrict__ w,
                          const float* __restrict__ iA, const float* __restrict__ iB,
                          float* __restrict__ out) {
    int idx = blockIdx.x * blockDim.x + threadIdx.x;
    if (idx >= BB * NC * DD) return;
    int d = idx % DD;
    int rest = idx / DD;
    int c = rest % NC;
    int b = rest / NC;
    float uu = u[d], ww = w[d];
    size_t base = ((size_t)b * TT + (size_t)c * LC) * DD + d;
    size_t o = ((size_t)b * NC + c) * DD + d;
    float a = iA[o], bd = iB[o];
#pragma unroll 4
    for (int t = 0; t < LC; t++) {
        size_t off = base + (size_t)t * DD;
        float kt = k[off], vt = v[off];
        float mx = fmaxf(uu + kt, ww);
        float e1 = __expf(-ww - mx);
        float e2 = __expf(uu + kt - mx);
        a  = fmaf(e1, a,  e2 * vt);
        bd = fmaf(e1, bd, e2);
        out[off] = f2tf_f((a / bd) * r[off]);
    }
}

// ---------------- launch ----------------------------------------------------
extern "C" void kernel_launch(void* const* d_in, const int* in_sizes, int n_in,
                              void* d_out, int out_size) {
    (void)in_sizes; (void)n_in; (void)out_size;
    const float* x   = (const float*)d_in[0];
    const float* Wk  = (const float*)d_in[1];
    const float* bk  = (const float*)d_in[2];
    const float* Wv  = (const float*)d_in[3];
    const float* bv  = (const float*)d_in[4];
    const float* Wr  = (const float*)d_in[5];
    const float* br  = (const float*)d_in[6];
    const float* Wo  = (const float*)d_in[7];
    const float* bo  = (const float*)d_in[8];
    const float* tmk = (const float*)d_in[9];
    const float* tmv = (const float*)d_in[10];
    const float* tmr = (const float*)d_in[11];
    const float* u   = (const float*)d_in[12];
    const float* w   = (const float*)d_in[13];
    float* out = (float*)d_out;

    float *kmix, *vmix, *rmix, *kb, *vb, *rb, *wkvr, *Wc, *P, *A, *Bc, *iA, *iB;
    cudaGetSymbolAddress((void**)&kmix, g_kmix);
    cudaGetSymbolAddress((void**)&vmix, g_vmix);
    cudaGetSymbolAddress((void**)&rmix, g_rmix);
    cudaGetSymbolAddress((void**)&kb,   g_k);
    cudaGetSymbolAddress((void**)&vb,   g_v);
    cudaGetSymbolAddress((void**)&rb,   g_r);
    cudaGetSymbolAddress((void**)&wkvr, g_wkvr);
    cudaGetSymbolAddress((void**)&Wc,   g_W);
    cudaGetSymbolAddress((void**)&P,    g_P);
    cudaGetSymbolAddress((void**)&A,    g_A);
    cudaGetSymbolAddress((void**)&Bc,   g_Bc);
    cudaGetSymbolAddress((void**)&iA,   g_iA);
    cudaGetSymbolAddress((void**)&iB,   g_iB);
    float* Wkc = Wc + 0 * (size_t)DD * DD;
    float* Wvc = Wc + 1 * (size_t)DD * DD;
    float* Wrc = Wc + 2 * (size_t)DD * DD;
    float* Woc = Wc + 3 * (size_t)DD * DD;

    cudaFuncSetAttribute(gemm_tf32, cudaFuncAttributeMaxDynamicSharedMemorySize, SMEM_BYTES);

    dim3 wcGrid((DD * DD / 4 + 255) / 256, 4);
    wconv_kernel<<<wcGrid, 256>>>(Wk, Wv, Wr, Wo, Wc);

    int mixBlocks = (MM * DD / 4 + 255) / 256;
    mix_kernel<<<mixBlocks, 256>>>(x, tmk, tmv, tmr, kmix, vmix, rmix);

    dim3 ggrid(DD / BN, MM / BM);   // (16, 64)
    gemm_tf32<<<ggrid, 256, SMEM_BYTES>>>(kmix, Wkc, bk, kb);
    gemm_tf32<<<ggrid, 256, SMEM_BYTES>>>(vmix, Wvc, bv, vb);
    gemm_tf32<<<ggrid, 256, SMEM_BYTES>>>(rmix, Wrc, br, rb);

    int scanThreads = BB * NC * DD;   // 524288
    wkv_pass1<<<scanThreads / 256, 256>>>(kb, vb, u, w, P, A, Bc);
    wkv_combine<<<(BB * DD + 255) / 256, 256>>>(P, A, Bc, iA, iB);
    wkv_pass3<<<scanThreads / 256, 256>>>(kb, vb, rb, u, w, iA, iB, wkvr);

    gemm_tf32<<<ggrid, 256, SMEM_BYTES>>>(wkvr, Woc, bo, out);
}

// round 5
// speedup vs baseline: 4.1545x; 1.8720x over previous
#include <cuda_runtime.h>
#include <cuda_fp16.h>
#include <cstdint>

#define BB 4
#define TT 4096
#define DD 2048
#define MM (BB*TT)   // 16384
#define NC 64
#define LC (TT/NC)

// ---------------- scratch (device globals) ----------------------------------
__device__ __half g_mixh[3][(size_t)MM*DD];   // kmix, vmix, rmix (fp16)
__device__ __half g_Wh  [4][(size_t)DD*DD];   // Wk, Wv, Wr, Wo (fp16)
__device__ float  g_kvr [3][(size_t)MM*DD];   // k, v, r (fp32 GEMM outputs)
__device__ __half g_wkvrh[(size_t)MM*DD];     // (a/b)*r in fp16
__device__ float g_P [(size_t)BB*NC*DD];
__device__ float g_A [(size_t)BB*NC*DD];
__device__ float g_Bc[(size_t)BB*NC*DD];
__device__ float g_iA[(size_t)BB*NC*DD];
__device__ float g_iB[(size_t)BB*NC*DD];

// ---------------- helpers -----------------------------------------------------
__device__ __forceinline__ void cp16(uint32_t dst, const void* src) {
    asm volatile("cp.async.cg.shared.global [%0], [%1], 16;" :: "r"(dst), "l"(src));
}
__device__ __forceinline__ void ldsm4(uint32_t& r0, uint32_t& r1, uint32_t& r2,
                                      uint32_t& r3, uint32_t addr) {
    asm volatile("ldmatrix.sync.aligned.m8n8.x4.shared.b16 {%0,%1,%2,%3}, [%4];"
                 : "=r"(r0), "=r"(r1), "=r"(r2), "=r"(r3) : "r"(addr));
}

// ---------------- weight convert (fp32 -> fp16) -------------------------------
__global__ void wconv_kernel(const float* __restrict__ w0, const float* __restrict__ w1,
                             const float* __restrict__ w2, const float* __restrict__ w3,
                             __half* __restrict__ out) {
    int i = blockIdx.x * blockDim.x + threadIdx.x;   // over DD*DD/4
    if (i >= DD * DD / 4) return;
    const float* src = (blockIdx.y == 0) ? w0 : (blockIdx.y == 1) ? w1 :
                       (blockIdx.y == 2) ? w2 : w3;
    float4 v = ((const float4*)src)[i];
    __half2 h01 = __floats2half2_rn(v.x, v.y);
    __half2 h23 = __floats2half2_rn(v.z, v.w);
    __half2* dst = (__half2*)(out + (size_t)blockIdx.y * DD * DD) + i * 2;
    dst[0] = h01; dst[1] = h23;
}

// ---------------- mix: time-shift + lerp (+silu for r) -> fp16 ----------------
__global__ void mix_kernel(const float* __restrict__ x,
                           const float* __restrict__ tmk,
                           const float* __restrict__ tmv,
                           const float* __restrict__ tmr,
                           __half* __restrict__ km,
                           __half* __restrict__ vm,
                           __half* __restrict__ rm) {
    int i4 = blockIdx.x * blockDim.x + threadIdx.x;
    if (i4 >= MM * DD / 4) return;
    size_t i = (size_t)i4 * 4;
    int m = (int)(i / DD);
    int d = (int)(i % DD);
    int t = m % TT;
    float4 xv = *(const float4*)(x + i);
    float4 xs = (t > 0) ? *(const float4*)(x + i - DD) : make_float4(0.f, 0.f, 0.f, 0.f);
    float4 mk = *(const float4*)(tmk + d);
    float4 mv = *(const float4*)(tmv + d);
    float4 mr = *(const float4*)(tmr + d);

    __half2 h01, h23;
    h01 = __floats2half2_rn(xv.x * mk.x + xs.x * (1.f - mk.x),
                            xv.y * mk.y + xs.y * (1.f - mk.y));
    h23 = __floats2half2_rn(xv.z * mk.z + xs.z * (1.f - mk.z),
                            xv.w * mk.w + xs.w * (1.f - mk.w));
    ((__half2*)(km + i))[0] = h01; ((__half2*)(km + i))[1] = h23;

    h01 = __floats2half2_rn(xv.x * mv.x + xs.x * (1.f - mv.x),
                            xv.y * mv.y + xs.y * (1.f - mv.y));
    h23 = __floats2half2_rn(xv.z * mv.z + xs.z * (1.f - mv.z),
                            xv.w * mv.w + xs.w * (1.f - mv.w));
    ((__half2*)(vm + i))[0] = h01; ((__half2*)(vm + i))[1] = h23;

    float s0, s1, s2, s3;
    s0 = xv.x * mr.x + xs.x * (1.f - mr.x); s0 = s0 / (1.f + __expf(-s0));
    s1 = xv.y * mr.y + xs.y * (1.f - mr.y); s1 = s1 / (1.f + __expf(-s1));
    s2 = xv.z * mr.z + xs.z * (1.f - mr.z); s2 = s2 / (1.f + __expf(-s2));
    s3 = xv.w * mr.w + xs.w * (1.f - mr.w); s3 = s3 / (1.f + __expf(-s3));
    ((__half2*)(rm + i))[0] = __floats2half2_rn(s0, s1);
    ((__half2*)(rm + i))[1] = __floats2half2_rn(s2, s3);
}

// ---------------- fp16 GEMM ----------------------------------------------------
// C[m,n] = sum_k A[m,k]*W[n,k] + bias[n]; A:[MM,DD] half, W:[DD,DD] half row-major
// BM=256, BN=128, BK=64 halves (128B rows). 256 threads, 4x2 warps of 64x64.
constexpr int BM = 256, BN = 128, BKH = 64, STAGES = 4;
constexpr int A_STAGE_B = BM * 128;       // 32768 bytes
constexpr int B_STAGE_B = BN * 128;       // 16384 bytes
constexpr int STAGE_B   = A_STAGE_B + B_STAGE_B;  // 49152
constexpr int GSMEM     = STAGES * STAGE_B;       // 196608

__global__ __launch_bounds__(256, 1)
void gemm_fp16(const __half* __restrict__ Abase, const __half* __restrict__ Wbase,
               const float* __restrict__ b0p, const float* __restrict__ b1p,
               const float* __restrict__ b2p, float* __restrict__ Cbase) {
    extern __shared__ char smem[];
    uint32_t sb = (uint32_t)__cvta_generic_to_shared(smem);
    const int K = DD, N = DD;

    int z = blockIdx.z;
    const __half* A = Abase + (size_t)z * MM * DD;
    const __half* W = Wbase + (size_t)z * DD * DD;
    const float* bias = (z == 0) ? b0p : (z == 1) ? b1p : b2p;
    float* C = Cbase + (size_t)z * MM * DD;

    int tid  = threadIdx.x;
    int m0   = blockIdx.y * BM;
    int n0   = blockIdx.x * BN;
    int warp = tid >> 5, lane = tid & 31;
    int wm = warp >> 1, wn = warp & 1;      // 4x2 warps, 64x64 tiles
    int g  = lane >> 2, tg = lane & 3;

    float acc[4][8][4];
#pragma unroll
    for (int a = 0; a < 4; a++)
#pragma unroll
        for (int b = 0; b < 8; b++)
#pragma unroll
            for (int c = 0; c < 4; c++) acc[a][b][c] = 0.f;

    auto load_stage = [&](int s, int ko) {   // ko in halves
        uint32_t base = sb + s * STAGE_B;
#pragma unroll
        for (int i = 0; i < 8; i++) {        // A: 2048 16B chunks
            int c  = tid + i * 256;
            int r  = c >> 3;
            int gp = c & 7;
            int pg = gp ^ (r & 7);
            cp16(base + (uint32_t)(r * 128 + pg * 16),
                 A + (size_t)(m0 + r) * K + ko + gp * 8);
        }
#pragma unroll
        for (int i = 0; i < 4; i++) {        // B: 1024 16B chunks
            int c  = tid + i * 256;
            int r  = c >> 3;
            int gp = c & 7;
            int pg = gp ^ (r & 7);
            cp16(base + (uint32_t)(A_STAGE_B + r * 128 + pg * 16),
                 W + (size_t)(n0 + r) * K + ko + gp * 8);
        }
        asm volatile("cp.async.commit_group;");
    };

    load_stage(0, 0);
    load_stage(1, BKH);
    load_stage(2, 2 * BKH);

    // ldmatrix lane mapping (precomputed pieces)
    int a_row16 = lane & 15;          // row within 16
    int a_khalf = lane >> 4;          // 0/1 -> 16B group offset
    int b_row   = ((lane >> 4) << 3) + (lane & 7);  // row within 16 (n)
    int b_khalf = (lane >> 3) & 1;

    const int KT = K / BKH;   // 32
    for (int kt = 0; kt < KT; kt++) {
        asm volatile("cp.async.wait_group 2;");
        __syncthreads();
        if (kt + 3 < KT) load_stage((kt + 3) & 3, (kt + 3) * BKH);

        uint32_t sa = sb + (kt & 3) * STAGE_B;
        uint32_t sbm = sa + A_STAGE_B;
#pragma unroll
        for (int ks = 0; ks < 4; ks++) {
            int kg = ks * 2;
            uint32_t af[4][4], bf[8][2];
#pragma unroll
            for (int mt = 0; mt < 4; mt++) {
                int mr = wm * 64 + mt * 16 + a_row16;
                int gp = (kg + a_khalf) ^ (mr & 7);
                ldsm4(af[mt][0], af[mt][1], af[mt][2], af[mt][3],
                      sa + (uint32_t)(mr * 128 + gp * 16));
            }
#pragma unroll
            for (int p = 0; p < 4; p++) {
                int nr = wn * 64 + p * 16 + b_row;
                int gp = (kg + b_khalf) ^ (nr & 7);
                ldsm4(bf[2 * p][0], bf[2 * p][1], bf[2 * p + 1][0], bf[2 * p + 1][1],
                      sbm + (uint32_t)(nr * 128 + gp * 16));
            }
#pragma unroll
            for (int mt = 0; mt < 4; mt++)
#pragma unroll
                for (int nt = 0; nt < 8; nt++) {
                    asm volatile(
                        "mma.sync.aligned.m16n8k16.row.col.f32.f16.f16.f32 "
                        "{%0,%1,%2,%3}, {%4,%5,%6,%7}, {%8,%9}, {%0,%1,%2,%3};"
                        : "+f"(acc[mt][nt][0]), "+f"(acc[mt][nt][1]),
                          "+f"(acc[mt][nt][2]), "+f"(acc[mt][nt][3])
                        : "r"(af[mt][0]), "r"(af[mt][1]), "r"(af[mt][2]), "r"(af[mt][3]),
                          "r"(bf[nt][0]), "r"(bf[nt][1]));
                }
        }
    }

#pragma unroll
    for (int mt = 0; mt < 4; mt++) {
#pragma unroll
        for (int nt = 0; nt < 8; nt++) {
            int m = m0 + wm * 64 + mt * 16 + g;
            int n = n0 + wn * 64 + nt * 8 + tg * 2;
            float b0 = bias[n], b1 = bias[n + 1];
            float2 v0 = make_float2(acc[mt][nt][0] + b0, acc[mt][nt][1] + b1);
            float2 v1 = make_float2(acc[mt][nt][2] + b0, acc[mt][nt][3] + b1);
            *(float2*)(C + (size_t)m * N + n)       = v0;
            *(float2*)(C + (size_t)(m + 8) * N + n) = v1;
        }
    }
}

// ---------------- chunked WKV scan ---------------------------------------------
__global__ void wkv_pass1(const float* __restrict__ k, const float* __restrict__ v,
                          const float* __restrict__ u, const float* __restrict__ w,
                          float* __restrict__ P, float* __restrict__ A,
                          float* __restrict__ Bc) {
    int idx = blockIdx.x * blockDim.x + threadIdx.x;
    if (idx >= BB * NC * DD) return;
    int d = idx % DD;
    int rest = idx / DD;
    int c = rest % NC;
    int b = rest / NC;
    float uu = u[d], ww = w[d];
    size_t base = ((size_t)b * TT + (size_t)c * LC) * DD + d;
    float Pp = 1.f, Aa = 0.f, Bb = 0.f;
#pragma unroll 4
    for (int t = 0; t < LC; t++) {
        size_t off = base + (size_t)t * DD;
        float kt = k[off], vt = v[off];
        float mx = fmaxf(uu + kt, ww);
        float e1 = __expf(-ww - mx);
        float e2 = __expf(uu + kt - mx);
        Aa = fmaf(e1, Aa, e2 * vt);
        Bb = fmaf(e1, Bb, e2);
        Pp *= e1;
    }
    size_t o = ((size_t)b * NC + c) * DD + d;
    P[o] = Pp; A[o] = Aa; Bc[o] = Bb;
}

__global__ void wkv_combine(const float* __restrict__ P, const float* __restrict__ A,
                            const float* __restrict__ Bc,
                            float* __restrict__ iA, float* __restrict__ iB) {
    int idx = blockIdx.x * blockDim.x + threadIdx.x;
    if (idx >= BB * DD) return;
    int d = idx % DD, b = idx / DD;
    float a = 0.f, bd = 0.f;
    for (int c = 0; c < NC; c++) {
        size_t o = ((size_t)b * NC + c) * DD + d;
        iA[o] = a; iB[o] = bd;
        a  = fmaf(P[o], a,  A[o]);
        bd = fmaf(P[o], bd, Bc[o]);
    }
}

__global__ void wkv_pass3(const float* __restrict__ k, const float* __restrict__ v,
                          const float* __restrict__ r,
                          const float* __restrict__ u, const float* __restrict__ w,
                          const float* __restrict__ iA, const float* __restrict__ iB,
                          __half* __restrict__ out) {
    int idx = blockIdx.x * blockDim.x + threadIdx.x;
    if (idx >= BB * NC * DD) return;
    int d = idx % DD;
    int rest = idx / DD;
    int c = rest % NC;
    int b = rest / NC;
    float uu = u[d], ww = w[d];
    size_t base = ((size_t)b * TT + (size_t)c * LC) * DD + d;
    size_t o = ((size_t)b * NC + c) * DD + d;
    float a = iA[o], bd = iB[o];
#pragma unroll 4
    for (int t = 0; t < LC; t++) {
        size_t off = base + (size_t)t * DD;
        float kt = k[off], vt = v[off];
        float mx = fmaxf(uu + kt, ww);
        float e1 = __expf(-ww - mx);
        float e2 = __expf(uu + kt - mx);
        a  = fmaf(e1, a,  e2 * vt);
        bd = fmaf(e1, bd, e2);
        out[off] = __float2half_rn((a / bd) * r[off]);
    }
}

// ---------------- launch ---------------------------------------------------------
extern "C" void kernel_launch(void* const* d_in, const int* in_sizes, int n_in,
                              void* d_out, int out_size) {
    (void)in_sizes; (void)n_in; (void)out_size;
    const float* x   = (const float*)d_in[0];
    const float* Wk  = (const float*)d_in[1];
    const float* bk  = (const float*)d_in[2];
    const float* Wv  = (const float*)d_in[3];
    const float* bv  = (const float*)d_in[4];
    const float* Wr  = (const float*)d_in[5];
    const float* br  = (const float*)d_in[6];
    const float* Wo  = (const float*)d_in[7];
    const float* bo  = (const float*)d_in[8];
    const float* tmk = (const float*)d_in[9];
    const float* tmv = (const float*)d_in[10];
    const float* tmr = (const float*)d_in[11];
    const float* u   = (const float*)d_in[12];
    const float* w   = (const float*)d_in[13];
    float* out = (float*)d_out;

    __half *mixh, *Wh, *wkvrh;
    float *kvr, *P, *A, *Bc, *iA, *iB;
    cudaGetSymbolAddress((void**)&mixh,  g_mixh);
    cudaGetSymbolAddress((void**)&Wh,    g_Wh);
    cudaGetSymbolAddress((void**)&kvr,   g_kvr);
    cudaGetSymbolAddress((void**)&wkvrh, g_wkvrh);
    cudaGetSymbolAddress((void**)&P,     g_P);
    cudaGetSymbolAddress((void**)&A,     g_A);
    cudaGetSymbolAddress((void**)&Bc,    g_Bc);
    cudaGetSymbolAddress((void**)&iA,    g_iA);
    cudaGetSymbolAddress((void**)&iB,    g_iB);
    __half* kmix = mixh + 0 * (size_t)MM * DD;
    float* kb = kvr + 0 * (size_t)MM * DD;
    float* vb = kvr + 1 * (size_t)MM * DD;
    float* rb = kvr + 2 * (size_t)MM * DD;

    cudaFuncSetAttribute(gemm_fp16, cudaFuncAttributeMaxDynamicSharedMemorySize, GSMEM);

    dim3 wcGrid((DD * DD / 4 + 255) / 256, 4);
    wconv_kernel<<<wcGrid, 256>>>(Wk, Wv, Wr, Wo, Wh);

    int mixBlocks = (MM * DD / 4 + 255) / 256;
    mix_kernel<<<mixBlocks, 256>>>(x, tmk, tmv, tmr,
                                   kmix, mixh + (size_t)MM * DD, mixh + 2 * (size_t)MM * DD);

    // fused k/v/r GEMMs via grid.z
    dim3 ggrid(DD / BN, MM / BM, 3);   // (16, 64, 3)
    gemm_fp16<<<ggrid, 256, GSMEM>>>(mixh, Wh, bk, bv, br, kvr);

    int scanThreads = BB * NC * DD;
    wkv_pass1<<<scanThreads / 256, 256>>>(kb, vb, u, w, P, A, Bc);
    wkv_combine<<<(BB * DD + 255) / 256, 256>>>(P, A, Bc, iA, iB);
    wkv_pass3<<<scanThreads / 256, 256>>>(kb, vb, rb, u, w, iA, iB, wkvrh);

    // final GEMM: z=1, A=wkvrh, W=Wo (4th slot), C=out
    dim3 fgrid(DD / BN, MM / BM, 1);
    gemm_fp16<<<fgrid, 256, GSMEM>>>(wkvrh, Wh + 3 * (size_t)DD * DD, bo, bo, bo, out);
}